// round 10
// baseline (speedup 1.0000x reference)
#include <cuda_runtime.h>
#include <cuda_bf16.h>
#include <math.h>
#include <cstdint>

// Problem constants
#define Bn    64
#define Sn    256
#define En    256
#define Hn    256          // per-direction hidden
#define Gn    1024         // 4*Hn
#define Tn    32
#define NTOK  (Bn*Sn)      // 16384
#define KTOT  768          // 3*En  (hi/lo split GEMM K)
#define KC    32           // K per chunk (bf16)
#define NCH   (KTOT/KC)    // 24 chunks

// ---------------- scratch (static device globals; no allocation) ----------------
__device__ __align__(256) __nv_bfloat16 gA[(size_t)NTOK*KTOT];   // [m][768]
__device__ __align__(256) __nv_bfloat16 gB[(size_t)2*Gn*KTOT];   // [dir][n][768]
__device__ float g_zx[2u*NTOK*Gn];             // Zx[dir][m][1024]
__device__ __align__(256) __nv_bfloat16 g_hx[2][2][Bn][512];  // [par][dir][b][hh|hl]
__device__ float g_hseq[2u*Bn*Sn*Hn];          // hseq[dir][b][t][j]
__device__ float g_feats[NTOK*Tn];             // feats[b][s][tag]
__device__ unsigned g_bc[2];                   // per-dir barrier counters
__device__ unsigned g_bg[2];                   // per-dir generation words

// ---------------- helpers -------------------------------------------------------
__device__ __forceinline__ uint32_t smem_u32(const void* p) {
    uint32_t a;
    asm("{ .reg .u64 t; cvta.to.shared.u64 t, %1; cvt.u32.u64 %0, t; }"
        : "=r"(a) : "l"(p));
    return a;
}
__device__ __forceinline__ uint32_t swz(uint32_t o) { return o ^ ((o >> 3) & 0x30); }

#define LDSM4(r, a) \
    asm volatile("ldmatrix.sync.aligned.m8n8.x4.shared.b16 {%0,%1,%2,%3}, [%4];" \
        : "=r"((r)[0]), "=r"((r)[1]), "=r"((r)[2]), "=r"((r)[3]) : "r"(a))

#define MMA16816(c, a, bv0, bv1) \
    asm volatile("mma.sync.aligned.m16n8k16.row.col.f32.bf16.bf16.f32 " \
        "{%0,%1,%2,%3}, {%4,%5,%6,%7}, {%8,%9}, {%0,%1,%2,%3};" \
        : "+f"((c)[0]), "+f"((c)[1]), "+f"((c)[2]), "+f"((c)[3]) \
        : "r"((a)[0]), "r"((a)[1]), "r"((a)[2]), "r"((a)[3]), "r"(bv0), "r"(bv1))

// ---------------- 0) reset sync state (runs each graph replay) ------------------
__global__ void k_reset()
{
    if (threadIdx.x < 2) { g_bc[threadIdx.x] = 0u; g_bg[threadIdx.x] = 0u; }
}

// ---------------- 1) embedding gather + hi/lo bf16 split ------------------------
__global__ void k_embed(const int* __restrict__ sent, const float* __restrict__ emb)
{
    int m = blockIdx.x;          // s*64+b
    int e = threadIdx.x;
    int b = m & 63, s = m >> 6;
    int w = sent[b * Sn + s];
    float x = emb[(size_t)w * En + e];
    __nv_bfloat16 xh = __float2bfloat16(x);
    __nv_bfloat16 xl = __float2bfloat16(x - __bfloat162float(xh));
    size_t base = (size_t)m * KTOT;
    gA[base + e]       = xh;
    gA[base + 256 + e] = xh;
    gA[base + 512 + e] = xl;
}

// ---------------- 1b) Wih hi/lo split: gB[dir][n] = [Wh | Wl | Wh] --------------
__global__ void k_wconv(const float* __restrict__ Wf, const float* __restrict__ Wb)
{
    int n   = blockIdx.x & (Gn - 1);
    int dir = blockIdx.x >> 10;
    int k   = threadIdx.x;
    const float* W = dir ? Wb : Wf;
    float w = W[(size_t)n * En + k];
    __nv_bfloat16 wh = __float2bfloat16(w);
    __nv_bfloat16 wl = __float2bfloat16(w - __bfloat162float(wh));
    size_t base = ((size_t)dir * Gn + n) * KTOT;
    gB[base + k]       = wh;
    gB[base + 256 + k] = wl;
    gB[base + 512 + k] = wh;
}

// ---------------- 2) HMMA GEMM: Zx = A·B^T + bias -------------------------------
__global__ __launch_bounds__(256)
void k_gemm_mma(const float* __restrict__ bias_f, const float* __restrict__ bias_b)
{
    __shared__ __align__(128) __nv_bfloat16 smA[2][128 * KC];
    __shared__ __align__(128) __nv_bfloat16 smB[2][128 * KC];

    const int tid  = threadIdx.x;
    const int wid  = tid >> 5, lane = tid & 31;
    const int bm   = blockIdx.x << 7;
    const int bn   = blockIdx.y << 7;
    const int dir  = blockIdx.z;
    const int wm   = (wid & 3) << 5;
    const int wn   = (wid >> 2) << 6;

    const char* Agc = (const char*)(gA + (size_t)bm * KTOT);
    const char* Bgc = (const char*)(gB + ((size_t)dir * Gn + bn) * KTOT);

    const int lrow = tid >> 2, lc16 = tid & 3;
    const uint32_t st0 = swz((uint32_t)lrow * 64 + (lc16 << 4));
    const uint32_t st1 = swz((uint32_t)(lrow + 64) * 64 + (lc16 << 4));
    const size_t ga0 = (size_t)lrow * (KTOT * 2) + (lc16 << 4);
    const size_t ga1 = (size_t)(lrow + 64) * (KTOT * 2) + (lc16 << 4);

    const uint32_t sA0 = smem_u32(smA[0]), sA1 = smem_u32(smA[1]);
    const uint32_t sB0 = smem_u32(smB[0]), sB1 = smem_u32(smB[1]);

    uint32_t offA[2][2], offB[4][2];
#pragma unroll
    for (int mt = 0; mt < 2; mt++)
#pragma unroll
        for (int s = 0; s < 2; s++)
            offA[mt][s] = swz((uint32_t)(wm + mt * 16 + (lane & 15)) * 64
                              + s * 32 + ((lane >> 4) << 4));
#pragma unroll
    for (int p = 0; p < 4; p++)
#pragma unroll
        for (int s = 0; s < 2; s++)
            offB[p][s] = swz((uint32_t)(wn + (p << 4) + (lane & 7)
                              + ((lane >> 4) << 3)) * 64
                              + s * 32 + (((lane >> 3) & 1) << 4));

    float acc[2][8][4];
#pragma unroll
    for (int i = 0; i < 2; i++)
#pragma unroll
        for (int j = 0; j < 8; j++)
#pragma unroll
            for (int q = 0; q < 4; q++) acc[i][j][q] = 0.f;

    {
        uint4 ra0 = *(const uint4*)(Agc + ga0);
        uint4 ra1 = *(const uint4*)(Agc + ga1);
        uint4 rb0 = *(const uint4*)(Bgc + ga0);
        uint4 rb1 = *(const uint4*)(Bgc + ga1);
        *(uint4*)((char*)smA[0] + st0) = ra0;
        *(uint4*)((char*)smA[0] + st1) = ra1;
        *(uint4*)((char*)smB[0] + st0) = rb0;
        *(uint4*)((char*)smB[0] + st1) = rb1;
    }
    __syncthreads();

    for (int ch = 0; ch < NCH; ch++) {
        const int cur = ch & 1;
        const bool more = (ch + 1) < NCH;
        uint4 ra0, ra1, rb0, rb1;
        if (more) {
            size_t ko = (size_t)(ch + 1) * (KC * 2);
            ra0 = *(const uint4*)(Agc + ga0 + ko);
            ra1 = *(const uint4*)(Agc + ga1 + ko);
            rb0 = *(const uint4*)(Bgc + ga0 + ko);
            rb1 = *(const uint4*)(Bgc + ga1 + ko);
        }

        const uint32_t sA = cur ? sA1 : sA0;
        const uint32_t sB = cur ? sB1 : sB0;
#pragma unroll
        for (int s = 0; s < 2; s++) {
            uint32_t a0[4], a1[4];
            LDSM4(a0, sA + offA[0][s]);
            LDSM4(a1, sA + offA[1][s]);
#pragma unroll
            for (int p = 0; p < 4; p++) {
                uint32_t bq[4];
                LDSM4(bq, sB + offB[p][s]);
                MMA16816(acc[0][2 * p],     a0, bq[0], bq[1]);
                MMA16816(acc[0][2 * p + 1], a0, bq[2], bq[3]);
                MMA16816(acc[1][2 * p],     a1, bq[0], bq[1]);
                MMA16816(acc[1][2 * p + 1], a1, bq[2], bq[3]);
            }
        }
        __syncthreads();
        if (more) {
            char* dA = (char*)smA[cur ^ 1];
            char* dB = (char*)smB[cur ^ 1];
            *(uint4*)(dA + st0) = ra0;
            *(uint4*)(dA + st1) = ra1;
            *(uint4*)(dB + st0) = rb0;
            *(uint4*)(dB + st1) = rb1;
        }
        __syncthreads();
    }

    const float* bias = dir ? bias_b : bias_f;
    float* C = g_zx + (size_t)dir * NTOK * Gn;
    const int g  = lane >> 2, tg = lane & 3;
#pragma unroll
    for (int mt = 0; mt < 2; mt++) {
        int r0 = bm + wm + mt * 16 + g;
#pragma unroll
        for (int nt = 0; nt < 8; nt++) {
            int cc = bn + wn + nt * 8 + 2 * tg;
            float2 bv = *(const float2*)(bias + cc);
            float* p0 = C + (size_t)r0 * Gn + cc;
            float2 o0 = make_float2(acc[mt][nt][0] + bv.x, acc[mt][nt][1] + bv.y);
            float2 o1 = make_float2(acc[mt][nt][2] + bv.x, acc[mt][nt][3] + bv.y);
            *(float2*)p0            = o0;
            *(float2*)(p0 + 8 * Gn) = o1;
        }
    }
}

// ---------------- 3) HMMA persistent LSTM: 32 blocks = (dir, 16 units) ----------
// Per step per block: gates[64 b][64 rows] = [hh|hl|hh] @ [Wh|Wh|Wl]^T (K=768).
// W resident in smem (96KB); A rebuilt each step from bf16 hi/lo h exchange.
// Gate-row order r = unit*4 + gate  →  a gate pair sits in adjacent frag cols.
#define A_SM_BYTES 98304
#define SMEM_L2 (2 * A_SM_BYTES)

__global__ __launch_bounds__(512)
void k_lstm2(const float* __restrict__ Whh_f, const float* __restrict__ Whh_b)
{
    extern __shared__ char sm[];
    const uint32_t sAb = smem_u32(sm);
    const uint32_t sWb = sAb + A_SM_BYTES;
    char* smW = sm + A_SM_BYTES;

    const int tid  = threadIdx.x;
    const int w    = tid >> 5, lane = tid & 31;
    const int dir  = blockIdx.x >> 4;
    const int blk  = blockIdx.x & 15;
    const int u0   = blk << 4;            // first unit owned
    const int wm   = (w & 3) << 4;        // batch-tile base (M=64)
    const int wn   = (w >> 2) << 4;       // gate-row tile base (N=64)

    // ---- fill W smem: hi/lo bf16, chunked (24 x [64 rows x 64B]) + swizzle ----
    const float* Whh = dir ? Whh_b : Whh_f;
    for (int e = tid; e < 64 * KTOT; e += 512) {
        int nr = e / KTOT, k = e - nr * KTOT;
        int g = nr & 3, uu = nr >> 2;
        float wv = Whh[(size_t)(g * 256 + u0 + uu) * 256 + (k & 255)];
        __nv_bfloat16 wh = __float2bfloat16(wv);
        __nv_bfloat16 val = (k < 512) ? wh
                           : __float2bfloat16(wv - __bfloat162float(wh));
        uint32_t off = (uint32_t)(k >> 5) * 4096
                     + swz((uint32_t)nr * 64 + (uint32_t)(k & 31) * 2);
        *(__nv_bfloat16*)(smW + off) = val;
    }

    // zero h exchange parity 0 (block zeroes its 1/16 slice of its dir)
    if (tid < 256)
        ((uint4*)g_hx[0][dir])[blk * 256 + tid] = make_uint4(0, 0, 0, 0);

    unsigned gen = 0;
    volatile unsigned* vgen = &g_bg[dir];

#define GRID_BAR() do {                                                   \
        __syncthreads();                                                  \
        if (tid == 0) {                                                   \
            __threadfence();                                              \
            unsigned tgt = ++gen;                                         \
            if (atomicAdd(&g_bc[dir], 1u) == 15u) {                       \
                g_bc[dir] = 0u;                                           \
                __threadfence();                                          \
                atomicAdd(&g_bg[dir], 1u);                                \
            } else {                                                      \
                while (*vgen < tgt) { }                                   \
                __threadfence();                                          \
            }                                                             \
        }                                                                 \
        __syncthreads();                                                  \
    } while (0)

    GRID_BAR();   // W loaded everywhere? (local) ; h0 zeros visible everywhere

    // frag smem offsets (R6-validated formulas, single m/n tile per warp)
    uint32_t offA[2], offB[2];
#pragma unroll
    for (int s = 0; s < 2; s++) {
        offA[s] = swz((uint32_t)(wm + (lane & 15)) * 64 + s * 32
                      + ((lane >> 4) << 4));
        offB[s] = swz((uint32_t)(wn + (lane & 7) + ((lane >> 4) << 3)) * 64
                      + s * 32 + (((lane >> 3) & 1) << 4));
    }

    // epilogue fixed indices
    const int q   = lane & 3;
    const int r0  = lane >> 2;
    const int b0  = wm + r0, b1 = b0 + 8;
    const int ga0 = (q & 1) ? 2 : 0;               // my cols' gates (ga0, ga0+1)
    const int jg0 = u0 + ((wn + 2 * q) >> 2);       // unit for nt=0 col pair
    const int jg1 = u0 + ((wn + 8 + 2 * q) >> 2);   // unit for nt=1 col pair
    const size_t zdir = (size_t)dir * NTOK * Gn;
    const bool leader = ((lane & 1) == 0);          // even lane computes c,h

#define ZLD(dst, t) do {                                                    \
        const float* zb = g_zx + zdir + ((size_t)((t) * Bn) << 10);         \
        dst[0] = zb[b0 * 1024 + (ga0    ) * 256 + jg0];                     \
        dst[1] = zb[b0 * 1024 + (ga0 + 1) * 256 + jg0];                     \
        dst[2] = zb[b1 * 1024 + (ga0    ) * 256 + jg0];                     \
        dst[3] = zb[b1 * 1024 + (ga0 + 1) * 256 + jg0];                     \
        dst[4] = zb[b0 * 1024 + (ga0    ) * 256 + jg1];                     \
        dst[5] = zb[b0 * 1024 + (ga0 + 1) * 256 + jg1];                     \
        dst[6] = zb[b1 * 1024 + (ga0    ) * 256 + jg1];                     \
        dst[7] = zb[b1 * 1024 + (ga0 + 1) * 256 + jg1];                     \
    } while (0)

    float zc[8], zn[8];
    { int t0 = dir ? (Sn - 1) : 0; ZLD(zc, t0); }

    float cst[4] = {0.f, 0.f, 0.f, 0.f};   // c for (nt0:b0,b1, nt1:b0,b1)

    for (int st = 0; st < Sn; ++st) {
        const int t   = dir ? (Sn - 1 - st) : st;
        const int par = st & 1;

        // ---- stage A = [hh | hl | hh] (96KB) from g_hx, swizzled chunks ----
        const __nv_bfloat16* hx = &g_hx[par][dir][0][0];
#pragma unroll
        for (int i = 0; i < 12; i++) {
            int a     = tid + (i << 9);
            int chunk = a >> 8;
            int row   = (a >> 2) & 63;
            int c16   = a & 3;
            int k0    = chunk * 32 + c16 * 8;
            int term  = k0 >> 8;
            int sel   = (term == 1) ? (256 + (k0 & 255)) : (k0 & 255);
            uint4 v = *(const uint4*)(hx + row * 512 + sel);
            *(uint4*)(sm + chunk * 4096 + swz((uint32_t)row * 64 + c16 * 16)) = v;
        }
        __syncthreads();

        // ---- GEMM: acc0 = rows wn..wn+7, acc1 = rows wn+8..wn+15 ----
        float acc0[4] = {0.f, 0.f, 0.f, 0.f};
        float acc1[4] = {0.f, 0.f, 0.f, 0.f};
#pragma unroll 4
        for (int ch = 0; ch < NCH; ch++) {
            uint32_t Ab = sAb + ch * 4096;
            uint32_t Bb = sWb + ch * 4096;
#pragma unroll
            for (int s = 0; s < 2; s++) {
                uint32_t af[4], bq[4];
                LDSM4(af, Ab + offA[s]);
                LDSM4(bq, Bb + offB[s]);
                MMA16816(acc0, af, bq[0], bq[1]);
                MMA16816(acc1, af, bq[2], bq[3]);
            }
        }

        // ---- fold in z (input-GEMM preactivations incl. bias) ----
        acc0[0] += zc[0]; acc0[1] += zc[1]; acc0[2] += zc[2]; acc0[3] += zc[3];
        acc1[0] += zc[4]; acc1[1] += zc[5]; acc1[2] += zc[6]; acc1[3] += zc[7];

        // prefetch next step's z (DRAM latency hides under epilogue+barrier)
        if (st + 1 < Sn) { int tn = dir ? (Sn - 2 - st) : (st + 1); ZLD(zn, tn); }

        // ---- exchange gate pairs: even lane (i,f) <-> odd lane (g,o) ----
        float o00 = __shfl_xor_sync(0xffffffffu, acc0[0], 1);
        float o01 = __shfl_xor_sync(0xffffffffu, acc0[1], 1);
        float o02 = __shfl_xor_sync(0xffffffffu, acc0[2], 1);
        float o03 = __shfl_xor_sync(0xffffffffu, acc0[3], 1);
        float o10 = __shfl_xor_sync(0xffffffffu, acc1[0], 1);
        float o11 = __shfl_xor_sync(0xffffffffu, acc1[1], 1);
        float o12 = __shfl_xor_sync(0xffffffffu, acc1[2], 1);
        float o13 = __shfl_xor_sync(0xffffffffu, acc1[3], 1);

        if (leader) {
            __nv_bfloat16* hxo = &g_hx[par ^ 1][dir][0][0];
#pragma unroll
            for (int v = 0; v < 4; v++) {
                float zi, zf, zg, zo;
                int b, j;
                switch (v) {
                    case 0: zi = acc0[0]; zf = acc0[1]; zg = o00; zo = o01;
                            b = b0; j = jg0; break;
                    case 1: zi = acc0[2]; zf = acc0[3]; zg = o02; zo = o03;
                            b = b1; j = jg0; break;
                    case 2: zi = acc1[0]; zf = acc1[1]; zg = o10; zo = o11;
                            b = b0; j = jg1; break;
                    default: zi = acc1[2]; zf = acc1[3]; zg = o12; zo = o13;
                            b = b1; j = jg1; break;
                }
                float ig = 1.f / (1.f + __expf(-zi));
                float fg = 1.f / (1.f + __expf(-zf));
                float gg = 1.f - 2.f / (__expf(2.f * zg) + 1.f);
                float og = 1.f / (1.f + __expf(-zo));
                float cn = fg * cst[v] + ig * gg;
                cst[v] = cn;
                float hv = og * (1.f - 2.f / (__expf(2.f * cn) + 1.f));

                __nv_bfloat16 hh = __float2bfloat16(hv);
                __nv_bfloat16 hl = __float2bfloat16(hv - __bfloat162float(hh));
                hxo[b * 512 + j]       = hh;
                hxo[b * 512 + 256 + j] = hl;
                g_hseq[(((size_t)dir * Bn + b) * Sn + t) * Hn + j] = hv;
            }
        }

#pragma unroll
        for (int i = 0; i < 8; i++) zc[i] = zn[i];

        GRID_BAR();
    }
#undef GRID_BAR
#undef ZLD
}

// ---------------- 4) feats = concat(h_f,h_b) @ Wout^T + bout -------------------
__global__ __launch_bounds__(256)
void k_feats(const float* __restrict__ Wout, const float* __restrict__ bout)
{
    __shared__ float Wt[128][33];

    const int tid = threadIdx.x;
    const int tag = tid & 31;
    const int ti  = tid >> 5;
    const int m   = blockIdx.x * 8 + ti;
    const int bb  = m & 63, ss = m >> 6;

    float acc = bout[tag];

    for (int cch = 0; cch < 4; cch++) {
        __syncthreads();
        for (int i = tid; i < 1024; i += 256) {
            int r = i >> 5;
            int k4 = i & 31;
            float4 w = *(const float4*)(Wout + (size_t)r * 512 + cch * 128 + (k4 << 2));
            Wt[(k4 << 2) + 0][r] = w.x;
            Wt[(k4 << 2) + 1][r] = w.y;
            Wt[(k4 << 2) + 2][r] = w.z;
            Wt[(k4 << 2) + 3][r] = w.w;
        }
        __syncthreads();

        const float* hrow;
        if (cch < 2)
            hrow = g_hseq + (((size_t)0 * Bn + bb) * Sn + ss) * Hn + cch * 128;
        else
            hrow = g_hseq + (((size_t)1 * Bn + bb) * Sn + ss) * Hn + (cch - 2) * 128;

#pragma unroll 8
        for (int k = 0; k < 128; k += 4) {
            float4 hv = *(const float4*)(hrow + k);
            acc += hv.x * Wt[k + 0][tag];
            acc += hv.y * Wt[k + 1][tag];
            acc += hv.z * Wt[k + 2][tag];
            acc += hv.w * Wt[k + 3][tag];
        }
    }
    g_feats[((size_t)(bb * Sn) + ss) * Tn + tag] = acc;
}

// ---------------- 5) Viterbi: one warp per batch ------------------------------
__global__ void k_viterbi(const float* __restrict__ trans, float* __restrict__ out)
{
    __shared__ float tr[32][32];
    __shared__ unsigned char bp[Sn][32];

    const int b   = blockIdx.x;
    const int tag = threadIdx.x;

    for (int p = 0; p < 32; p++) tr[p][tag] = trans[p * 32 + tag];
    __syncwarp();

    float v = (tag == 0) ? 0.f : -10000.f;
    const float* fb = g_feats + (size_t)b * Sn * Tn;

    for (int t = 0; t < Sn; t++) {
        float best = -3.4e38f; int arg = 0;
#pragma unroll
        for (int p = 0; p < 32; p++) {
            float vp = __shfl_sync(0xffffffffu, v, p);
            float sc = vp + tr[p][tag];
            if (sc > best) { best = sc; arg = p; }
        }
        bp[t][tag] = (unsigned char)arg;
        v = best + fb[t * 32 + tag];
    }

    float term = v + tr[0][tag];
    float best = -3.4e38f; int lt = 0;
#pragma unroll
    for (int p = 0; p < 32; p++) {
        float tp = __shfl_sync(0xffffffffu, term, p);
        if (tp > best) { best = tp; lt = p; }
    }
    __syncwarp();

    if (tag == 0) {
        int cur = lt;
        for (int t = Sn - 1; t >= 1; --t) {
            out[b * Sn + t] = (float)cur;
            cur = bp[t][cur];
        }
        out[b * Sn + 0] = (float)cur;
        out[NTOK + b]   = best;
    }
}

// ---------------- launcher -----------------------------------------------------
extern "C" void kernel_launch(void* const* d_in, const int* in_sizes, int n_in,
                              void* d_out, int out_size)
{
    const int*   sent  = (const int*)  d_in[0];
    const float* embed = (const float*)d_in[1];
    const float* Wih_f = (const float*)d_in[2];
    const float* Whh_f = (const float*)d_in[3];
    const float* b_f   = (const float*)d_in[4];
    const float* Wih_b = (const float*)d_in[5];
    const float* Whh_b = (const float*)d_in[6];
    const float* b_b   = (const float*)d_in[7];
    const float* Wout  = (const float*)d_in[8];
    const float* bout  = (const float*)d_in[9];
    const float* trans = (const float*)d_in[10];
    float* out = (float*)d_out;
    (void)in_sizes; (void)n_in; (void)out_size;

    // 0) reset barrier state (fresh every graph replay)
    k_reset<<<1, 32>>>();

    // 1) embedding + bf16 hi/lo split of A; W split (tiny)
    k_embed<<<NTOK, 256>>>(sent, embed);
    k_wconv<<<2 * Gn, 256>>>(Wih_f, Wih_b);

    // 2) tensor-core (HMMA) input GEMM, both directions
    dim3 gg(NTOK / 128, Gn / 128, 2);
    k_gemm_mma<<<gg, 256>>>(b_f, b_b);

    // 3) HMMA persistent LSTM: 32 blocks, smem-resident hi/lo Whh
    cudaFuncSetAttribute(k_lstm2, cudaFuncAttributeMaxDynamicSharedMemorySize,
                         (int)SMEM_L2);
    k_lstm2<<<32, 512, SMEM_L2>>>(Whh_f, Whh_b);

    // 4) emissions
    k_feats<<<NTOK / 8, 256>>>(Wout, bout);

    // 5) viterbi decode + writeback (paths as float, then scores)
    k_viterbi<<<Bn, 32>>>(trans, out);
}

// round 12
// speedup vs baseline: 1.5758x; 1.5758x over previous
#include <cuda_runtime.h>
#include <cuda_bf16.h>
#include <math.h>
#include <cstdint>

// Problem constants
#define Bn    64
#define Sn    256
#define En    256
#define Hn    256          // per-direction hidden
#define Gn    1024         // 4*Hn
#define Tn    32
#define NTOK  (Bn*Sn)      // 16384
#define KTOT  768          // 3*En  (hi/lo split GEMM K)
#define KC    32           // K per chunk (bf16)
#define NCH   (KTOT/KC)    // 24 chunks

// ---------------- scratch (static device globals; no allocation) ----------------
__device__ __align__(256) __nv_bfloat16 gA[(size_t)NTOK*KTOT];   // [m][768]
__device__ __align__(256) __nv_bfloat16 gB[(size_t)2*Gn*KTOT];   // [dir][n][768]
__device__ float g_zx[2u*NTOK*Gn];             // z[dir][t][j][g][b]  (transposed!)
__device__ float g_h[2*2*Bn*Hn];               // h[parity][dir][b][j]
__device__ float g_hseq[2u*Sn*Bn*Hn];          // hseq[dir][t][b][j]  (t-major!)
__device__ float g_feats[NTOK*Tn];             // feats[b][s][tag]
__device__ unsigned g_bc[2];                   // per-dir barrier counters
__device__ unsigned g_bg[2];                   // per-dir generation words

// ---------------- helpers -------------------------------------------------------
__device__ __forceinline__ uint32_t smem_u32(const void* p) {
    uint32_t a;
    asm("{ .reg .u64 t; cvta.to.shared.u64 t, %1; cvt.u32.u64 %0, t; }"
        : "=r"(a) : "l"(p));
    return a;
}
__device__ __forceinline__ uint32_t swz(uint32_t o) { return o ^ ((o >> 3) & 0x30); }

#define LDSM4(r, a) \
    asm volatile("ldmatrix.sync.aligned.m8n8.x4.shared.b16 {%0,%1,%2,%3}, [%4];" \
        : "=r"((r)[0]), "=r"((r)[1]), "=r"((r)[2]), "=r"((r)[3]) : "r"(a))

#define MMA16816(c, a, bv0, bv1) \
    asm volatile("mma.sync.aligned.m16n8k16.row.col.f32.bf16.bf16.f32 " \
        "{%0,%1,%2,%3}, {%4,%5,%6,%7}, {%8,%9}, {%0,%1,%2,%3};" \
        : "+f"((c)[0]), "+f"((c)[1]), "+f"((c)[2]), "+f"((c)[3]) \
        : "r"((a)[0]), "r"((a)[1]), "r"((a)[2]), "r"((a)[3]), "r"(bv0), "r"(bv1))

// ---------------- 1) embedding gather + hi/lo bf16 split ------------------------
__global__ void k_embed(const int* __restrict__ sent, const float* __restrict__ emb)
{
    int m = blockIdx.x;          // s*64+b
    int e = threadIdx.x;
    int b = m & 63, s = m >> 6;
    int w = sent[b * Sn + s];
    float x = emb[(size_t)w * En + e];
    __nv_bfloat16 xh = __float2bfloat16(x);
    __nv_bfloat16 xl = __float2bfloat16(x - __bfloat162float(xh));
    size_t base = (size_t)m * KTOT;
    gA[base + e]       = xh;
    gA[base + 256 + e] = xh;
    gA[base + 512 + e] = xl;
}

// ---------------- 1b) Wih hi/lo split: gB[dir][n] = [Wh | Wl | Wh] --------------
__global__ void k_wconv(const float* __restrict__ Wf, const float* __restrict__ Wb)
{
    int n   = blockIdx.x & (Gn - 1);
    int dir = blockIdx.x >> 10;
    int k   = threadIdx.x;
    const float* W = dir ? Wb : Wf;
    float w = W[(size_t)n * En + k];
    __nv_bfloat16 wh = __float2bfloat16(w);
    __nv_bfloat16 wl = __float2bfloat16(w - __bfloat162float(wh));
    size_t base = ((size_t)dir * Gn + n) * KTOT;
    gB[base + k]       = wh;
    gB[base + 256 + k] = wl;
    gB[base + 512 + k] = wh;
}

// ---------------- 2) HMMA GEMM: Zx = A·B^T + bias, transposed epilogue ----------
__global__ __launch_bounds__(256)
void k_gemm_mma(const float* __restrict__ bias_f, const float* __restrict__ bias_b)
{
    __shared__ __align__(128) __nv_bfloat16 smA[2][128 * KC];
    __shared__ __align__(128) __nv_bfloat16 smB[2][128 * KC];

    const int tid  = threadIdx.x;
    const int wid  = tid >> 5, lane = tid & 31;
    const int bm   = blockIdx.x << 7;
    const int bn   = blockIdx.y << 7;
    const int dir  = blockIdx.z;
    const int wm   = (wid & 3) << 5;
    const int wn   = (wid >> 2) << 6;

    const char* Agc = (const char*)(gA + (size_t)bm * KTOT);
    const char* Bgc = (const char*)(gB + ((size_t)dir * Gn + bn) * KTOT);

    const int lrow = tid >> 2, lc16 = tid & 3;
    const uint32_t st0 = swz((uint32_t)lrow * 64 + (lc16 << 4));
    const uint32_t st1 = swz((uint32_t)(lrow + 64) * 64 + (lc16 << 4));
    const size_t ga0 = (size_t)lrow * (KTOT * 2) + (lc16 << 4);
    const size_t ga1 = (size_t)(lrow + 64) * (KTOT * 2) + (lc16 << 4);

    const uint32_t sA0 = smem_u32(smA[0]), sA1 = smem_u32(smA[1]);
    const uint32_t sB0 = smem_u32(smB[0]), sB1 = smem_u32(smB[1]);

    uint32_t offA[2][2], offB[4][2];
#pragma unroll
    for (int mt = 0; mt < 2; mt++)
#pragma unroll
        for (int s = 0; s < 2; s++)
            offA[mt][s] = swz((uint32_t)(wm + mt * 16 + (lane & 15)) * 64
                              + s * 32 + ((lane >> 4) << 4));
#pragma unroll
    for (int p = 0; p < 4; p++)
#pragma unroll
        for (int s = 0; s < 2; s++)
            offB[p][s] = swz((uint32_t)(wn + (p << 4) + (lane & 7)
                              + ((lane >> 4) << 3)) * 64
                              + s * 32 + (((lane >> 3) & 1) << 4));

    float acc[2][8][4];
#pragma unroll
    for (int i = 0; i < 2; i++)
#pragma unroll
        for (int j = 0; j < 8; j++)
#pragma unroll
            for (int q = 0; q < 4; q++) acc[i][j][q] = 0.f;

    {
        uint4 ra0 = *(const uint4*)(Agc + ga0);
        uint4 ra1 = *(const uint4*)(Agc + ga1);
        uint4 rb0 = *(const uint4*)(Bgc + ga0);
        uint4 rb1 = *(const uint4*)(Bgc + ga1);
        *(uint4*)((char*)smA[0] + st0) = ra0;
        *(uint4*)((char*)smA[0] + st1) = ra1;
        *(uint4*)((char*)smB[0] + st0) = rb0;
        *(uint4*)((char*)smB[0] + st1) = rb1;
    }
    __syncthreads();

    for (int ch = 0; ch < NCH; ch++) {
        const int cur = ch & 1;
        const bool more = (ch + 1) < NCH;
        uint4 ra0, ra1, rb0, rb1;
        if (more) {
            size_t ko = (size_t)(ch + 1) * (KC * 2);
            ra0 = *(const uint4*)(Agc + ga0 + ko);
            ra1 = *(const uint4*)(Agc + ga1 + ko);
            rb0 = *(const uint4*)(Bgc + ga0 + ko);
            rb1 = *(const uint4*)(Bgc + ga1 + ko);
        }

        const uint32_t sA = cur ? sA1 : sA0;
        const uint32_t sB = cur ? sB1 : sB0;
#pragma unroll
        for (int s = 0; s < 2; s++) {
            uint32_t a0[4], a1[4];
            LDSM4(a0, sA + offA[0][s]);
            LDSM4(a1, sA + offA[1][s]);
#pragma unroll
            for (int p = 0; p < 4; p++) {
                uint32_t bq[4];
                LDSM4(bq, sB + offB[p][s]);
                MMA16816(acc[0][2 * p],     a0, bq[0], bq[1]);
                MMA16816(acc[0][2 * p + 1], a0, bq[2], bq[3]);
                MMA16816(acc[1][2 * p],     a1, bq[0], bq[1]);
                MMA16816(acc[1][2 * p + 1], a1, bq[2], bq[3]);
            }
        }
        __syncthreads();
        if (more) {
            char* dA = (char*)smA[cur ^ 1];
            char* dB = (char*)smB[cur ^ 1];
            *(uint4*)(dA + st0) = ra0;
            *(uint4*)(dA + st1) = ra1;
            *(uint4*)(dB + st0) = rb0;
            *(uint4*)(dB + st1) = rb1;
        }
        __syncthreads();
    }

    // transposed epilogue: z[dir][t][j][g][b]  (b-runs contiguous, 4x32B/inst)
    const float* bias = dir ? bias_b : bias_f;
    const int g  = lane >> 2, tg = lane & 3;
#pragma unroll
    for (int mt = 0; mt < 2; mt++) {
        int m0  = bm + wm + mt * 16 + g;
        int t0  = m0 >> 6, b0v = m0 & 63;          // b0v <= 55, b0v+8 same t
        float* tbase = g_zx + (((size_t)dir * Sn + t0) << 16);
#pragma unroll
        for (int nt = 0; nt < 8; nt++) {
            int n0 = bn + wn + nt * 8 + 2 * tg;
#pragma unroll
            for (int dq = 0; dq < 2; dq++) {
                int n  = n0 + dq;
                int g2 = n >> 8, j = n & 255;
                float bv = bias[n];
                float* base = tbase + (size_t)j * 256 + g2 * 64;
                base[b0v]     = acc[mt][nt][dq]     + bv;
                base[b0v + 8] = acc[mt][nt][2 + dq] + bv;
            }
        }
    }
}

// ---------------- 3) persistent bidirectional LSTM (128 blocks, 512 thr) --------
// R6 architecture + coalesced smem z tiles + float4 h publication.
#define RS 264
#define KHO 132
#define ZS 1040            // padded z tile: 4 j-rows x 260
#define SMEM_LSTM ((16*RS + Bn*RS + 2*ZS) * sizeof(float))

__global__ __launch_bounds__(512)
void k_lstm(const float* __restrict__ Whh_f, const float* __restrict__ Whh_b)
{
    extern __shared__ float smx[];
    float* Ws = smx;                    // [4 gates][4 jj][RS]
    float* hs = smx + 16 * RS;          // [64 b][RS]
    float* zs = smx + 16 * RS + Bn * RS;// [2][ZS] ping-pong z tiles

    const int tid = threadIdx.x;
    const int dir = blockIdx.x >> 6;
    const int j0  = (blockIdx.x & 63) << 2;
    const int b   = tid >> 3;
    const int jj  = (tid >> 1) & 3;
    const int kh  = tid & 1;

    const float* Whh = dir ? Whh_b : Whh_f;
    for (int idx = tid; idx < 4096; idx += 512) {
        int g = idx >> 10, j2 = (idx >> 8) & 3, k = idx & 255;
        Ws[(g * 4 + j2) * RS + (k >> 7) * KHO + (k & 127)] =
            Whh[(g * Hn + j0 + j2) * Hn + k];
    }

    // zero h(parity 0) slice
    if (kh == 0)
        g_h[(0 * 2 + dir) * (Bn * Hn) + b * Hn + j0 + jj] = 0.f;

    // cooperative coalesced load of first z tile into zs[0]
    {
        int t0 = dir ? (Sn - 1) : 0;
        const float* zt = g_zx + (((size_t)dir * Sn + t0) << 16) + (size_t)j0 * 256;
        int i = tid * 2;
        float2 v = *(const float2*)(zt + i);
        *(float2*)(zs + (i >> 8) * 260 + (i & 255)) = v;
    }

    unsigned gen = 0;
    volatile unsigned* vgen = &g_bg[dir];
    {   // pick up persistent generation (monotonic across graph replays)
        gen = *vgen;
    }

#define GRID_BAR() do {                                                   \
        __syncthreads();                                                  \
        if (tid == 0) {                                                   \
            __threadfence();                                              \
            unsigned tgt = ++gen;                                         \
            if (atomicAdd(&g_bc[dir], 1u) == 63u) {                       \
                g_bc[dir] = 0u;                                           \
                __threadfence();                                          \
                atomicAdd(&g_bg[dir], 1u);                                \
            } else {                                                      \
                while (*vgen < tgt) { }                                   \
                __threadfence();                                          \
            }                                                             \
        }                                                                 \
        __syncthreads();                                                  \
    } while (0)

    GRID_BAR();   // h0 + first z tile visible / staged

    float c = 0.f;
    const float* hrow = hs + b * RS + kh * KHO;
    const float* w0 = Ws + (0 * 4 + jj) * RS + kh * KHO;
    const float* w1 = Ws + (1 * 4 + jj) * RS + kh * KHO;
    const float* w2 = Ws + (2 * 4 + jj) * RS + kh * KHO;
    const float* w3 = Ws + (3 * 4 + jj) * RS + kh * KHO;

    for (int st = 0; st < Sn; ++st) {
        const int t   = dir ? (Sn - 1 - st) : st;
        const int par = st & 1;

        // stage h[par][dir] (64KB) into smem, split-k padded layout
        const float4* hp = (const float4*)(g_h + (par * 2 + dir) * (Bn * Hn));
#pragma unroll
        for (int i = 0; i < 8; i++) {
            int li = tid + (i << 9);
            float4 v = hp[li];
            int bb = li >> 6, kk = li & 63;
            int khh = kk >> 5, kr = (kk & 31) << 2;
            *(float4*)(hs + bb * RS + khh * KHO + kr) = v;
        }
        __syncthreads();

        // z from smem tile (conflict-free padded layout; kh==0 only)
        const float* zcur = zs + (st & 1) * ZS;
        float a0 = 0.f, a1 = 0.f, a2 = 0.f, a3 = 0.f;
        if (kh == 0) {
            a0 = zcur[jj * 260 + 0   + b];
            a1 = zcur[jj * 260 + 64  + b];
            a2 = zcur[jj * 260 + 128 + b];
            a3 = zcur[jj * 260 + 192 + b];
        }

#pragma unroll 8
        for (int k = 0; k < 128; k += 4) {
            float4 hv = *(const float4*)(hrow + k);
            float4 wv;
            wv = *(const float4*)(w0 + k);
            a0 += hv.x * wv.x + hv.y * wv.y + hv.z * wv.z + hv.w * wv.w;
            wv = *(const float4*)(w1 + k);
            a1 += hv.x * wv.x + hv.y * wv.y + hv.z * wv.z + hv.w * wv.w;
            wv = *(const float4*)(w2 + k);
            a2 += hv.x * wv.x + hv.y * wv.y + hv.z * wv.z + hv.w * wv.w;
            wv = *(const float4*)(w3 + k);
            a3 += hv.x * wv.x + hv.y * wv.y + hv.z * wv.z + hv.w * wv.w;
        }

        // cooperative prefetch of next z tile (hides under shfl+epilogue+barrier)
        if (st + 1 < Sn) {
            int tn2 = dir ? (Sn - 2 - st) : (st + 1);
            const float* zt = g_zx + (((size_t)dir * Sn + tn2) << 16)
                            + (size_t)j0 * 256;
            int i = tid * 2;
            float2 v = *(const float2*)(zt + i);
            *(float2*)(zs + ((st + 1) & 1) * ZS + (i >> 8) * 260 + (i & 255)) = v;
        }

        // combine k-halves (symmetric: both lanes get identical sums)
        a0 += __shfl_xor_sync(0xffffffffu, a0, 1);
        a1 += __shfl_xor_sync(0xffffffffu, a1, 1);
        a2 += __shfl_xor_sync(0xffffffffu, a2, 1);
        a3 += __shfl_xor_sync(0xffffffffu, a3, 1);

        // gates via fast exp (MUFU)
        float ig = 1.f / (1.f + __expf(-a0));
        float fg = 1.f / (1.f + __expf(-a1));
        float gg = 1.f - 2.f / (__expf(2.f * a2) + 1.f);
        float og = 1.f / (1.f + __expf(-a3));
        c = fg * c + ig * gg;
        float hn = og * (1.f - 2.f / (__expf(2.f * c) + 1.f));

        // gather the 4 jj values; one writer lane per b does 2x STG.128
        float h1 = __shfl_down_sync(0xffffffffu, hn, 2);
        float h2 = __shfl_down_sync(0xffffffffu, hn, 4);
        float h3 = __shfl_down_sync(0xffffffffu, hn, 6);
        if ((tid & 7) == 0) {
            float4 hv4 = make_float4(hn, h1, h2, h3);
            *(float4*)(&g_h[((par ^ 1) * 2 + dir) * (Bn * Hn) + b * Hn + j0]) = hv4;
            *(float4*)(&g_hseq[(((size_t)dir * Sn + t) * Bn + b) * Hn + j0]) = hv4;
        }

        GRID_BAR();
    }
#undef GRID_BAR
}

// ---------------- 4) feats = concat(h_f,h_b) @ Wout^T + bout -------------------
__global__ __launch_bounds__(256)
void k_feats(const float* __restrict__ Wout, const float* __restrict__ bout)
{
    __shared__ float Wt[128][33];

    const int tid = threadIdx.x;
    const int tag = tid & 31;
    const int ti  = tid >> 5;
    const int m   = blockIdx.x * 8 + ti;
    const int bb  = m & 63, ss = m >> 6;

    float acc = bout[tag];

    for (int cch = 0; cch < 4; cch++) {
        __syncthreads();
        for (int i = tid; i < 1024; i += 256) {
            int r = i >> 5;
            int k4 = i & 31;
            float4 w = *(const float4*)(Wout + (size_t)r * 512 + cch * 128 + (k4 << 2));
            Wt[(k4 << 2) + 0][r] = w.x;
            Wt[(k4 << 2) + 1][r] = w.y;
            Wt[(k4 << 2) + 2][r] = w.z;
            Wt[(k4 << 2) + 3][r] = w.w;
        }
        __syncthreads();

        const float* hrow;
        if (cch < 2)
            hrow = g_hseq + (((size_t)0 * Sn + ss) * Bn + bb) * Hn + cch * 128;
        else
            hrow = g_hseq + (((size_t)1 * Sn + ss) * Bn + bb) * Hn + (cch - 2) * 128;

#pragma unroll 8
        for (int k = 0; k < 128; k += 4) {
            float4 hv = *(const float4*)(hrow + k);
            acc += hv.x * Wt[k + 0][tag];
            acc += hv.y * Wt[k + 1][tag];
            acc += hv.z * Wt[k + 2][tag];
            acc += hv.w * Wt[k + 3][tag];
        }
    }
    g_feats[((size_t)(bb * Sn) + ss) * Tn + tag] = acc;
}

// ---------------- 5) Viterbi: one warp per batch, smem broadcast ---------------
__global__ void k_viterbi(const float* __restrict__ trans, float* __restrict__ out)
{
    __shared__ float vs[32];
    __shared__ unsigned char bp[Sn][32];

    const int b   = blockIdx.x;
    const int tag = threadIdx.x;

    float trc[32];                 // my column of trans (prev -> my tag)
#pragma unroll
    for (int p = 0; p < 32; p++) trc[p] = trans[p * 32 + tag];

    float v = (tag == 0) ? 0.f : -10000.f;
    const float* fb = g_feats + (size_t)b * Sn * Tn;

    for (int t = 0; t < Sn; t++) {
        vs[tag] = v;
        __syncwarp();
        float best = -3.4e38f; int arg = 0;
#pragma unroll
        for (int p = 0; p < 32; p++) {    // ascending + strict '>' = first argmax
            float sc = vs[p] + trc[p];
            if (sc > best) { best = sc; arg = p; }
        }
        __syncwarp();
        bp[t][tag] = (unsigned char)arg;
        v = best + fb[t * 32 + tag];
    }

    float term = v + trc[0];              // terminal uses trans[0, :]
    vs[tag] = term;
    __syncwarp();
    float best = -3.4e38f; int lt = 0;
#pragma unroll
    for (int p = 0; p < 32; p++) {
        float tp = vs[p];
        if (tp > best) { best = tp; lt = p; }
    }
    __syncwarp();

    if (tag == 0) {
        int cur = lt;
        for (int t = Sn - 1; t >= 1; --t) {
            out[b * Sn + t] = (float)cur;
            cur = bp[t][cur];
        }
        out[b * Sn + 0] = (float)cur;
        out[NTOK + b]   = best;
    }
}

// ---------------- launcher -----------------------------------------------------
extern "C" void kernel_launch(void* const* d_in, const int* in_sizes, int n_in,
                              void* d_out, int out_size)
{
    const int*   sent  = (const int*)  d_in[0];
    const float* embed = (const float*)d_in[1];
    const float* Wih_f = (const float*)d_in[2];
    const float* Whh_f = (const float*)d_in[3];
    const float* b_f   = (const float*)d_in[4];
    const float* Wih_b = (const float*)d_in[5];
    const float* Whh_b = (const float*)d_in[6];
    const float* b_b   = (const float*)d_in[7];
    const float* Wout  = (const float*)d_in[8];
    const float* bout  = (const float*)d_in[9];
    const float* trans = (const float*)d_in[10];
    float* out = (float*)d_out;
    (void)in_sizes; (void)n_in; (void)out_size;

    // 1) embedding + bf16 hi/lo split of A; W split (tiny)
    k_embed<<<NTOK, 256>>>(sent, embed);
    k_wconv<<<2 * Gn, 256>>>(Wih_f, Wih_b);

    // 2) tensor-core (HMMA) input GEMM, both directions, transposed z epilogue
    dim3 gg(NTOK / 128, Gn / 128, 2);
    k_gemm_mma<<<gg, 256>>>(b_f, b_b);

    // 3) persistent recurrent kernel (128 co-resident blocks, per-dir barriers)
    cudaFuncSetAttribute(k_lstm, cudaFuncAttributeMaxDynamicSharedMemorySize,
                         (int)SMEM_LSTM);
    k_lstm<<<128, 512, SMEM_LSTM>>>(Whh_f, Whh_b);

    // 4) emissions
    k_feats<<<NTOK / 8, 256>>>(Wout, bout);

    // 5) viterbi decode + writeback (paths as float, then scores)
    k_viterbi<<<Bn, 32>>>(trans, out);
}

// round 13
// speedup vs baseline: 1.9897x; 1.2627x over previous
#include <cuda_runtime.h>
#include <cuda_bf16.h>
#include <math.h>
#include <cstdint>

// Problem constants
#define Bn    64
#define Sn    256
#define En    256
#define Hn    256          // per-direction hidden
#define Gn    1024         // 4*Hn
#define Tn    32
#define NTOK  (Bn*Sn)      // 16384
#define KTOT  768          // 3*En  (hi/lo split GEMM K)
#define KC    32           // K per chunk (bf16)
#define NCH   (KTOT/KC)    // 24 chunks

// ---------------- scratch (static device globals; no allocation) ----------------
__device__ __align__(256) __nv_bfloat16 gA[(size_t)NTOK*KTOT];   // [m][768]
__device__ __align__(256) __nv_bfloat16 gB[(size_t)2*Gn*KTOT];   // [dir][n][768]
__device__ float g_zx[2u*NTOK*Gn];             // z[dir][t][j][g][b]  (transposed)
__device__ float g_h[2*2*Bn*Hn];               // h[parity][dir][b][j]
__device__ float g_hseq[2u*Sn*Bn*Hn];          // hseq[dir][t][b][j]  (t-major)
__device__ float g_feats[NTOK*Tn];             // feats[b][s][tag]
__device__ unsigned g_bc[2];                   // per-dir barrier counters
__device__ unsigned g_bg[2];                   // per-dir generation words (monotonic)

// ---------------- helpers -------------------------------------------------------
__device__ __forceinline__ uint32_t smem_u32(const void* p) {
    uint32_t a;
    asm("{ .reg .u64 t; cvta.to.shared.u64 t, %1; cvt.u32.u64 %0, t; }"
        : "=r"(a) : "l"(p));
    return a;
}
__device__ __forceinline__ uint32_t swz(uint32_t o) { return o ^ ((o >> 3) & 0x30); }

#define LDSM4(r, a) \
    asm volatile("ldmatrix.sync.aligned.m8n8.x4.shared.b16 {%0,%1,%2,%3}, [%4];" \
        : "=r"((r)[0]), "=r"((r)[1]), "=r"((r)[2]), "=r"((r)[3]) : "r"(a))

#define MMA16816(c, a, bv0, bv1) \
    asm volatile("mma.sync.aligned.m16n8k16.row.col.f32.bf16.bf16.f32 " \
        "{%0,%1,%2,%3}, {%4,%5,%6,%7}, {%8,%9}, {%0,%1,%2,%3};" \
        : "+f"((c)[0]), "+f"((c)[1]), "+f"((c)[2]), "+f"((c)[3]) \
        : "r"((a)[0]), "r"((a)[1]), "r"((a)[2]), "r"((a)[3]), "r"(bv0), "r"(bv1))

// ---------------- 1) embedding gather + hi/lo bf16 split ------------------------
__global__ void k_embed(const int* __restrict__ sent, const float* __restrict__ emb)
{
    int m = blockIdx.x;          // s*64+b
    int e = threadIdx.x;
    int b = m & 63, s = m >> 6;
    int w = sent[b * Sn + s];
    float x = emb[(size_t)w * En + e];
    __nv_bfloat16 xh = __float2bfloat16(x);
    __nv_bfloat16 xl = __float2bfloat16(x - __bfloat162float(xh));
    size_t base = (size_t)m * KTOT;
    gA[base + e]       = xh;
    gA[base + 256 + e] = xh;
    gA[base + 512 + e] = xl;
}

// ---------------- 1b) Wih hi/lo split: gB[dir][n] = [Wh | Wl | Wh] --------------
__global__ void k_wconv(const float* __restrict__ Wf, const float* __restrict__ Wb)
{
    int n   = blockIdx.x & (Gn - 1);
    int dir = blockIdx.x >> 10;
    int k   = threadIdx.x;
    const float* W = dir ? Wb : Wf;
    float w = W[(size_t)n * En + k];
    __nv_bfloat16 wh = __float2bfloat16(w);
    __nv_bfloat16 wl = __float2bfloat16(w - __bfloat162float(wh));
    size_t base = ((size_t)dir * Gn + n) * KTOT;
    gB[base + k]       = wh;
    gB[base + 256 + k] = wl;
    gB[base + 512 + k] = wh;
}

// ---------------- 2) HMMA GEMM: Zx = A·B^T + bias, transposed epilogue ----------
__global__ __launch_bounds__(256)
void k_gemm_mma(const float* __restrict__ bias_f, const float* __restrict__ bias_b)
{
    __shared__ __align__(128) __nv_bfloat16 smA[2][128 * KC];
    __shared__ __align__(128) __nv_bfloat16 smB[2][128 * KC];

    const int tid  = threadIdx.x;
    const int wid  = tid >> 5, lane = tid & 31;
    const int bm   = blockIdx.x << 7;
    const int bn   = blockIdx.y << 7;
    const int dir  = blockIdx.z;
    const int wm   = (wid & 3) << 5;
    const int wn   = (wid >> 2) << 6;

    const char* Agc = (const char*)(gA + (size_t)bm * KTOT);
    const char* Bgc = (const char*)(gB + ((size_t)dir * Gn + bn) * KTOT);

    const int lrow = tid >> 2, lc16 = tid & 3;
    const uint32_t st0 = swz((uint32_t)lrow * 64 + (lc16 << 4));
    const uint32_t st1 = swz((uint32_t)(lrow + 64) * 64 + (lc16 << 4));
    const size_t ga0 = (size_t)lrow * (KTOT * 2) + (lc16 << 4);
    const size_t ga1 = (size_t)(lrow + 64) * (KTOT * 2) + (lc16 << 4);

    const uint32_t sA0 = smem_u32(smA[0]), sA1 = smem_u32(smA[1]);
    const uint32_t sB0 = smem_u32(smB[0]), sB1 = smem_u32(smB[1]);

    uint32_t offA[2][2], offB[4][2];
#pragma unroll
    for (int mt = 0; mt < 2; mt++)
#pragma unroll
        for (int s = 0; s < 2; s++)
            offA[mt][s] = swz((uint32_t)(wm + mt * 16 + (lane & 15)) * 64
                              + s * 32 + ((lane >> 4) << 4));
#pragma unroll
    for (int p = 0; p < 4; p++)
#pragma unroll
        for (int s = 0; s < 2; s++)
            offB[p][s] = swz((uint32_t)(wn + (p << 4) + (lane & 7)
                              + ((lane >> 4) << 3)) * 64
                              + s * 32 + (((lane >> 3) & 1) << 4));

    float acc[2][8][4];
#pragma unroll
    for (int i = 0; i < 2; i++)
#pragma unroll
        for (int j = 0; j < 8; j++)
#pragma unroll
            for (int q = 0; q < 4; q++) acc[i][j][q] = 0.f;

    {
        uint4 ra0 = *(const uint4*)(Agc + ga0);
        uint4 ra1 = *(const uint4*)(Agc + ga1);
        uint4 rb0 = *(const uint4*)(Bgc + ga0);
        uint4 rb1 = *(const uint4*)(Bgc + ga1);
        *(uint4*)((char*)smA[0] + st0) = ra0;
        *(uint4*)((char*)smA[0] + st1) = ra1;
        *(uint4*)((char*)smB[0] + st0) = rb0;
        *(uint4*)((char*)smB[0] + st1) = rb1;
    }
    __syncthreads();

    for (int ch = 0; ch < NCH; ch++) {
        const int cur = ch & 1;
        const bool more = (ch + 1) < NCH;
        uint4 ra0, ra1, rb0, rb1;
        if (more) {
            size_t ko = (size_t)(ch + 1) * (KC * 2);
            ra0 = *(const uint4*)(Agc + ga0 + ko);
            ra1 = *(const uint4*)(Agc + ga1 + ko);
            rb0 = *(const uint4*)(Bgc + ga0 + ko);
            rb1 = *(const uint4*)(Bgc + ga1 + ko);
        }

        const uint32_t sA = cur ? sA1 : sA0;
        const uint32_t sB = cur ? sB1 : sB0;
#pragma unroll
        for (int s = 0; s < 2; s++) {
            uint32_t a0[4], a1[4];
            LDSM4(a0, sA + offA[0][s]);
            LDSM4(a1, sA + offA[1][s]);
#pragma unroll
            for (int p = 0; p < 4; p++) {
                uint32_t bq[4];
                LDSM4(bq, sB + offB[p][s]);
                MMA16816(acc[0][2 * p],     a0, bq[0], bq[1]);
                MMA16816(acc[0][2 * p + 1], a0, bq[2], bq[3]);
                MMA16816(acc[1][2 * p],     a1, bq[0], bq[1]);
                MMA16816(acc[1][2 * p + 1], a1, bq[2], bq[3]);
            }
        }
        __syncthreads();
        if (more) {
            char* dA = (char*)smA[cur ^ 1];
            char* dB = (char*)smB[cur ^ 1];
            *(uint4*)(dA + st0) = ra0;
            *(uint4*)(dA + st1) = ra1;
            *(uint4*)(dB + st0) = rb0;
            *(uint4*)(dB + st1) = rb1;
        }
        __syncthreads();
    }

    // transposed epilogue: z[dir][t][j][g][b]  (b-runs contiguous)
    const float* bias = dir ? bias_b : bias_f;
    const int g  = lane >> 2, tg = lane & 3;
#pragma unroll
    for (int mt = 0; mt < 2; mt++) {
        int m0  = bm + wm + mt * 16 + g;
        int t0  = m0 >> 6, b0v = m0 & 63;
        float* tbase = g_zx + (((size_t)dir * Sn + t0) << 16);
#pragma unroll
        for (int nt = 0; nt < 8; nt++) {
            int n0 = bn + wn + nt * 8 + 2 * tg;
#pragma unroll
            for (int dq = 0; dq < 2; dq++) {
                int n  = n0 + dq;
                int g2 = n >> 8, j = n & 255;
                float bv = bias[n];
                float* base = tbase + (size_t)j * 256 + g2 * 64;
                base[b0v]     = acc[mt][nt][dq]     + bv;
                base[b0v + 8] = acc[mt][nt][2 + dq] + bv;
            }
        }
    }
}

// ---------------- 3) persistent LSTM: register-blocked 4b x 4g tiles ------------
// 128 blocks = (dir, 4 hidden units). 512 thr = (bq 0..15 = warp, jj 0..3, ks 0..7).
// Thread: 4 batches x 4 gates over its 32-k segment -> 8 LDS.128 per 64 FFMA.
// k-segment stride 36 floats => conflict-free octet phases for W, h, staging.
#define WROW 288           // 8 segs x 36
#define HROW 288
#define ZS 1040
#define SMEM_LSTM ((16*WROW + Bn*HROW + 2*ZS) * sizeof(float))

__global__ __launch_bounds__(512)
void k_lstm(const float* __restrict__ Whh_f, const float* __restrict__ Whh_b)
{
    extern __shared__ float smx[];
    float* Ws = smx;                         // [16 rows (g*4+jj)][WROW]
    float* hs = smx + 16 * WROW;             // [64 b][HROW]
    float* zs = smx + 16 * WROW + Bn * HROW; // [2][ZS]

    const int tid = threadIdx.x;
    const int dir = blockIdx.x >> 6;
    const int j0  = (blockIdx.x & 63) << 2;
    const int bq  = tid >> 5;                // warp id = batch quad
    const int jj  = (tid >> 3) & 3;
    const int ks  = tid & 7;                 // k segment (32 k each)
    const int b0q = bq << 2;

    // ---- stage Whh slice: Ws[(g*4+j2)][ks2*36 + kk] ----
    const float* Whh = dir ? Whh_b : Whh_f;
    for (int idx = tid; idx < 4096; idx += 512) {
        int g = idx >> 10, j2 = (idx >> 8) & 3, k = idx & 255;
        Ws[(g * 4 + j2) * WROW + (k >> 5) * 36 + (k & 31)] =
            Whh[(g * Hn + j0 + j2) * Hn + k];
    }

    // zero h(parity 0) slice: 256 floats owned by this block
    if (tid < 256) {
        int b = tid >> 2, j2 = tid & 3;
        g_h[(0 * 2 + dir) * (Bn * Hn) + b * Hn + j0 + j2] = 0.f;
    }

    // first z tile into zs[0]  (z[dir][t][jrel][g][b], 1024 floats)
    {
        int t0 = dir ? (Sn - 1) : 0;
        const float* zt = g_zx + (((size_t)dir * Sn + t0) << 16) + (size_t)j0 * 256;
        int i = tid * 2;
        float2 v = *(const float2*)(zt + i);
        *(float2*)(zs + (i >> 8) * 260 + (i & 255)) = v;
    }

    unsigned gen = 0;
    volatile unsigned* vgen = &g_bg[dir];
    gen = *vgen;                  // monotonic across graph replays

#define GRID_BAR() do {                                                   \
        __syncthreads();                                                  \
        if (tid == 0) {                                                   \
            __threadfence();                                              \
            unsigned tgt = ++gen;                                         \
            if (atomicAdd(&g_bc[dir], 1u) == 63u) {                       \
                g_bc[dir] = 0u;                                           \
                __threadfence();                                          \
                atomicAdd(&g_bg[dir], 1u);                                \
            } else {                                                      \
                while (*vgen < tgt) { }                                   \
                __threadfence();                                          \
            }                                                             \
        }                                                                 \
        __syncthreads();                                                  \
    } while (0)

    GRID_BAR();   // h0 + first z tile visible

    float c = 0.f;                      // valid in lanes with ks<4 (b = b0q+ks)
    const float* hb = hs + b0q * HROW + ks * 36;
    const float* wj = Ws + jj * WROW + ks * 36;   // + g*4*WROW per gate

    for (int st = 0; st < Sn; ++st) {
        const int t   = dir ? (Sn - 1 - st) : st;
        const int par = st & 1;

        // ---- stage h[par][dir] (64KB) into segmented layout ----
        const float4* hp = (const float4*)(g_h + (par * 2 + dir) * (Bn * Hn));
#pragma unroll
        for (int i = 0; i < 8; i++) {
            int li = tid + (i << 9);
            float4 v = hp[li];
            int bb = li >> 6, k4 = li & 63;          // k4 = float4 index in row
            *(float4*)(hs + bb * HROW + (k4 >> 3) * 36 + ((k4 & 7) << 2)) = v;
        }
        __syncthreads();

        // ---- register-blocked 4b x 4g over this thread's 32-k segment ----
        float acc[4][4];
#pragma unroll
        for (int i = 0; i < 4; i++)
#pragma unroll
            for (int g = 0; g < 4; g++) acc[i][g] = 0.f;

#pragma unroll
        for (int kk = 0; kk < 32; kk += 4) {
            float4 hv[4], wv[4];
#pragma unroll
            for (int i = 0; i < 4; i++)
                hv[i] = *(const float4*)(hb + i * HROW + kk);
#pragma unroll
            for (int g = 0; g < 4; g++)
                wv[g] = *(const float4*)(wj + g * (4 * WROW) + kk);
#pragma unroll
            for (int i = 0; i < 4; i++)
#pragma unroll
                for (int g = 0; g < 4; g++)
                    acc[i][g] += hv[i].x * wv[g].x + hv[i].y * wv[g].y
                               + hv[i].z * wv[g].z + hv[i].w * wv[g].w;
        }

        // prefetch next z tile (hides under combine+epilogue+barrier)
        if (st + 1 < Sn) {
            int tn2 = dir ? (Sn - 2 - st) : (st + 1);
            const float* zt = g_zx + (((size_t)dir * Sn + tn2) << 16)
                            + (size_t)j0 * 256;
            int i = tid * 2;
            float2 v = *(const float2*)(zt + i);
            *(float2*)(zs + ((st + 1) & 1) * ZS + (i >> 8) * 260 + (i & 255)) = v;
        }

        // ---- combine 8 k-segments: xor-tree within each octet ----
#pragma unroll
        for (int m = 1; m <= 4; m <<= 1)
#pragma unroll
            for (int i = 0; i < 4; i++)
#pragma unroll
                for (int g = 0; g < 4; g++)
                    acc[i][g] += __shfl_xor_sync(0xffffffffu, acc[i][g], m);

        // ---- epilogue: lanes ks<4 each own batch b = b0q+ks ----
        if (ks < 4) {
            const float* zcur = zs + (st & 1) * ZS + jj * 260;
            int b = b0q + ks;
            float zi = zcur[0   + b] + acc[ks][0];
            float zf = zcur[64  + b] + acc[ks][1];
            float zg = zcur[128 + b] + acc[ks][2];
            float zo = zcur[192 + b] + acc[ks][3];

            float ig = 1.f / (1.f + __expf(-zi));
            float fg = 1.f / (1.f + __expf(-zf));
            float gg = 1.f - 2.f / (__expf(2.f * zg) + 1.f);
            float og = 1.f / (1.f + __expf(-zo));
            c = fg * c + ig * gg;
            float hn = og * (1.f - 2.f / (__expf(2.f * c) + 1.f));

            int j = j0 + jj;
            g_h[((par ^ 1) * 2 + dir) * (Bn * Hn) + b * Hn + j] = hn;
            g_hseq[(((size_t)dir * Sn + t) * Bn + b) * Hn + j] = hn;
        }

        GRID_BAR();
    }
#undef GRID_BAR
}

// ---------------- 4) feats = concat(h_f,h_b) @ Wout^T + bout -------------------
__global__ __launch_bounds__(256)
void k_feats(const float* __restrict__ Wout, const float* __restrict__ bout)
{
    __shared__ float Wt[128][33];

    const int tid = threadIdx.x;
    const int tag = tid & 31;
    const int ti  = tid >> 5;
    const int m   = blockIdx.x * 8 + ti;
    const int bb  = m & 63, ss = m >> 6;

    float acc = bout[tag];

    for (int cch = 0; cch < 4; cch++) {
        __syncthreads();
        for (int i = tid; i < 1024; i += 256) {
            int r = i >> 5;
            int k4 = i & 31;
            float4 w = *(const float4*)(Wout + (size_t)r * 512 + cch * 128 + (k4 << 2));
            Wt[(k4 << 2) + 0][r] = w.x;
            Wt[(k4 << 2) + 1][r] = w.y;
            Wt[(k4 << 2) + 2][r] = w.z;
            Wt[(k4 << 2) + 3][r] = w.w;
        }
        __syncthreads();

        const float* hrow;
        if (cch < 2)
            hrow = g_hseq + (((size_t)0 * Sn + ss) * Bn + bb) * Hn + cch * 128;
        else
            hrow = g_hseq + (((size_t)1 * Sn + ss) * Bn + bb) * Hn + (cch - 2) * 128;

#pragma unroll 8
        for (int k = 0; k < 128; k += 4) {
            float4 hv = *(const float4*)(hrow + k);
            acc += hv.x * Wt[k + 0][tag];
            acc += hv.y * Wt[k + 1][tag];
            acc += hv.z * Wt[k + 2][tag];
            acc += hv.w * Wt[k + 3][tag];
        }
    }
    g_feats[((size_t)(bb * Sn) + ss) * Tn + tag] = acc;
}

// ---------------- 5) Viterbi: one warp per batch, smem broadcast ---------------
__global__ void k_viterbi(const float* __restrict__ trans, float* __restrict__ out)
{
    __shared__ float vs[32];
    __shared__ unsigned char bp[Sn][32];

    const int b   = blockIdx.x;
    const int tag = threadIdx.x;

    float trc[32];
#pragma unroll
    for (int p = 0; p < 32; p++) trc[p] = trans[p * 32 + tag];

    float v = (tag == 0) ? 0.f : -10000.f;
    const float* fb = g_feats + (size_t)b * Sn * Tn;

    for (int t = 0; t < Sn; t++) {
        vs[tag] = v;
        __syncwarp();
        float best = -3.4e38f; int arg = 0;
#pragma unroll
        for (int p = 0; p < 32; p++) {
            float sc = vs[p] + trc[p];
            if (sc > best) { best = sc; arg = p; }
        }
        __syncwarp();
        bp[t][tag] = (unsigned char)arg;
        v = best + fb[t * 32 + tag];
    }

    float term = v + trc[0];
    vs[tag] = term;
    __syncwarp();
    float best = -3.4e38f; int lt = 0;
#pragma unroll
    for (int p = 0; p < 32; p++) {
        float tp = vs[p];
        if (tp > best) { best = tp; lt = p; }
    }
    __syncwarp();

    if (tag == 0) {
        int cur = lt;
        for (int t = Sn - 1; t >= 1; --t) {
            out[b * Sn + t] = (float)cur;
            cur = bp[t][cur];
        }
        out[b * Sn + 0] = (float)cur;
        out[NTOK + b]   = best;
    }
}

// ---------------- launcher -----------------------------------------------------
extern "C" void kernel_launch(void* const* d_in, const int* in_sizes, int n_in,
                              void* d_out, int out_size)
{
    const int*   sent  = (const int*)  d_in[0];
    const float* embed = (const float*)d_in[1];
    const float* Wih_f = (const float*)d_in[2];
    const float* Whh_f = (const float*)d_in[3];
    const float* b_f   = (const float*)d_in[4];
    const float* Wih_b = (const float*)d_in[5];
    const float* Whh_b = (const float*)d_in[6];
    const float* b_b   = (const float*)d_in[7];
    const float* Wout  = (const float*)d_in[8];
    const float* bout  = (const float*)d_in[9];
    const float* trans = (const float*)d_in[10];
    float* out = (float*)d_out;
    (void)in_sizes; (void)n_in; (void)out_size;

    // 1) embedding + bf16 hi/lo split of A; W split (tiny)
    k_embed<<<NTOK, 256>>>(sent, embed);
    k_wconv<<<2 * Gn, 256>>>(Wih_f, Wih_b);

    // 2) tensor-core (HMMA) input GEMM, both directions, transposed z epilogue
    dim3 gg(NTOK / 128, Gn / 128, 2);
    k_gemm_mma<<<gg, 256>>>(b_f, b_b);

    // 3) persistent recurrent kernel (register-blocked, crossbar-balanced)
    cudaFuncSetAttribute(k_lstm, cudaFuncAttributeMaxDynamicSharedMemorySize,
                         (int)SMEM_LSTM);
    k_lstm<<<128, 512, SMEM_LSTM>>>(Whh_f, Whh_b);

    // 4) emissions
    k_feats<<<NTOK / 8, 256>>>(Wout, bout);

    // 5) viterbi decode + writeback (paths as float, then scores)
    k_viterbi<<<Bn, 32>>>(trans, out);
}